// round 1
// baseline (speedup 1.0000x reference)
#include <cuda_runtime.h>

// Problem constants (from reference)
#define L0_TOP 0.05f
#define D_CONST 0.0075f
#define DS 0.005f
#define N_STEPS 10
#define T_OUT (N_STEPS + 1)

// ODE on the 12-float live state: y = [r0..r2, R00,R01,R02, R10,R11,R12, R20,R21,R22]
// dr   = R[:,2]  (elements 2,5,8 of R)
// dR[i,0] = -uy*R[i,2];  dR[i,1] = ux*R[i,2];  dR[i,2] = uy*R[i,0] - ux*R[i,1]
__device__ __forceinline__ void ode_fn(const float* __restrict__ y,
                                       float ux, float uy,
                                       float* __restrict__ d) {
    d[0] = y[3 + 2];
    d[1] = y[3 + 5];
    d[2] = y[3 + 8];
#pragma unroll
    for (int i = 0; i < 3; i++) {
        float Ri0 = y[3 + i * 3 + 0];
        float Ri1 = y[3 + i * 3 + 1];
        float Ri2 = y[3 + i * 3 + 2];
        d[3 + i * 3 + 0] = -uy * Ri2;
        d[3 + i * 3 + 1] =  ux * Ri2;
        d[3 + i * 3 + 2] =  uy * Ri0 - ux * Ri1;
    }
}

__device__ __forceinline__ void write_row(float* __restrict__ out, int t, int b, int B,
                                          const float* __restrict__ y,
                                          float ux, float uy) {
    size_t base = (size_t)t * (size_t)B * 14 + (size_t)b * 14;
    float2* o = reinterpret_cast<float2*>(out + base);  // base is even -> 8B aligned
    o[0] = make_float2(y[0],  y[1]);
    o[1] = make_float2(y[2],  y[3]);
    o[2] = make_float2(y[4],  y[5]);
    o[3] = make_float2(y[6],  y[7]);
    o[4] = make_float2(y[8],  y[9]);
    o[5] = make_float2(y[10], y[11]);
    o[6] = make_float2(ux,    uy);
}

__global__ void __launch_bounds__(256) sfr_rk4_kernel(
    const float* __restrict__ actions,  // [B, 3]
    float* __restrict__ out,            // [11, B, 14]
    int B)
{
    int b = blockIdx.x * blockDim.x + threadIdx.x;
    if (b >= B) return;

    float a1 = actions[b * 3 + 1];
    float a2 = actions[b * 3 + 2];
    const float ld = L0_TOP * D_CONST;   // 0.000375
    float ux = a2 / (-ld);
    float uy = a1 / ( ld);

    // y0: r = 0, R = I
    float y[12] = {0.f, 0.f, 0.f,
                   1.f, 0.f, 0.f,
                   0.f, 1.f, 0.f,
                   0.f, 0.f, 1.f};

    const float dt = DS;
    const float half_dt = 0.5f * dt;
    const float dt6 = dt * (1.0f / 6.0f);

    write_row(out, 0, b, B, y, ux, uy);

#pragma unroll 1
    for (int s = 0; s < N_STEPS; s++) {
        float k1[12], k2[12], k3[12], k4[12], tmp[12];

        ode_fn(y, ux, uy, k1);
#pragma unroll
        for (int i = 0; i < 12; i++) tmp[i] = y[i] + half_dt * k1[i];
        ode_fn(tmp, ux, uy, k2);
#pragma unroll
        for (int i = 0; i < 12; i++) tmp[i] = y[i] + half_dt * k2[i];
        ode_fn(tmp, ux, uy, k3);
#pragma unroll
        for (int i = 0; i < 12; i++) tmp[i] = y[i] + dt * k3[i];
        ode_fn(tmp, ux, uy, k4);
#pragma unroll
        for (int i = 0; i < 12; i++)
            y[i] = y[i] + dt6 * (k1[i] + 2.0f * k2[i] + 2.0f * k3[i] + k4[i]);

        write_row(out, s + 1, b, B, y, ux, uy);
    }
}

extern "C" void kernel_launch(void* const* d_in, const int* in_sizes, int n_in,
                              void* d_out, int out_size) {
    const float* actions = (const float*)d_in[0];
    float* out = (float*)d_out;
    int B = in_sizes[0] / 3;  // actions is [B, 3]

    int threads = 256;
    int blocks = (B + threads - 1) / threads;
    sfr_rk4_kernel<<<blocks, threads>>>(actions, out, B);
}

// round 2
// speedup vs baseline: 2.7684x; 2.7684x over previous
#include <cuda_runtime.h>

// Problem constants (from reference)
#define L0_TOP 0.05f
#define D_CONST 0.0075f
#define DS 0.005f
#define N_STEPS 10

#define TPB 256
#define ROW_PAD 15            // 14 payload floats padded to 15 (odd -> conflict-free STS)
#define FLOATS_PER_BLOCK (TPB * 14)          // 3584
#define VEC4_PER_BLOCK   (FLOATS_PER_BLOCK/4) // 896

// ODE on the 12-float live state: y = [r0..r2, R00..R22]
// dr = R[:,2]; dR[i,0] = -uy*R[i,2]; dR[i,1] = ux*R[i,2]; dR[i,2] = uy*R[i,0] - ux*R[i,1]
__device__ __forceinline__ void ode_fn(const float* __restrict__ y,
                                       float ux, float uy,
                                       float* __restrict__ d) {
    d[0] = y[3 + 2];
    d[1] = y[3 + 5];
    d[2] = y[3 + 8];
#pragma unroll
    for (int i = 0; i < 3; i++) {
        float Ri0 = y[3 + i * 3 + 0];
        float Ri1 = y[3 + i * 3 + 1];
        float Ri2 = y[3 + i * 3 + 2];
        d[3 + i * 3 + 0] = -uy * Ri2;
        d[3 + i * 3 + 1] =  ux * Ri2;
        d[3 + i * 3 + 2] =  uy * Ri0 - ux * Ri1;
    }
}

__global__ void __launch_bounds__(TPB) sfr_rk4_kernel(
    const float* __restrict__ actions,  // [B, 3]
    float* __restrict__ out,            // [11, B, 14]
    int B)
{
    __shared__ float sh[TPB * ROW_PAD];

    const int tid = threadIdx.x;
    const int blockStart = blockIdx.x * TPB;
    const int b = blockStart + tid;
    const bool active = (b < B);
    const int cnt = min(TPB, B - blockStart);

    float ux = 0.f, uy = 0.f;
    if (active) {
        float a1 = actions[b * 3 + 1];
        float a2 = actions[b * 3 + 2];
        const float ld = L0_TOP * D_CONST;   // 0.000375
        ux = a2 / (-ld);
        uy = a1 / ( ld);
    }

    // y0: r = 0, R = I
    float y[12] = {0.f, 0.f, 0.f,
                   1.f, 0.f, 0.f,
                   0.f, 1.f, 0.f,
                   0.f, 0.f, 1.f};

    const float dt = DS;
    const float half_dt = 0.5f * dt;
    const float dt6 = dt * (1.0f / 6.0f);

#pragma unroll 1
    for (int t = 0; t <= N_STEPS; t++) {
        // ---- advance state (skip on t==0: emit y0 first) ----
        if (t > 0) {
            float k1[12], k2[12], k3[12], k4[12], tmp[12];
            ode_fn(y, ux, uy, k1);
#pragma unroll
            for (int i = 0; i < 12; i++) tmp[i] = y[i] + half_dt * k1[i];
            ode_fn(tmp, ux, uy, k2);
#pragma unroll
            for (int i = 0; i < 12; i++) tmp[i] = y[i] + half_dt * k2[i];
            ode_fn(tmp, ux, uy, k3);
#pragma unroll
            for (int i = 0; i < 12; i++) tmp[i] = y[i] + dt * k3[i];
            ode_fn(tmp, ux, uy, k4);
#pragma unroll
            for (int i = 0; i < 12; i++)
                y[i] = y[i] + dt6 * (k1[i] + 2.0f * k2[i] + 2.0f * k3[i] + k4[i]);
        }

        // ---- stage this row into smem (stride-15 rows: conflict-free) ----
        {
            float* s = sh + tid * ROW_PAD;
#pragma unroll
            for (int i = 0; i < 12; i++) s[i] = y[i];
            s[12] = ux;
            s[13] = uy;
        }
        __syncthreads();

        // ---- cooperative coalesced flush: 3584 floats as 896 float4 ----
        {
            size_t gbase = (size_t)t * (size_t)B * 14 + (size_t)blockStart * 14;
            if (cnt == TPB) {
                float4* og = reinterpret_cast<float4*>(out + gbase); // 16B aligned
#pragma unroll
                for (int k = tid; k < VEC4_PER_BLOCK; k += TPB) {
                    int g = 4 * k;
                    int e = g / 14;          // magic-mul division
                    int c = g - e * 14;
                    float4 v;
                    v.x = sh[e * ROW_PAD + c]; if (++c == 14) { c = 0; ++e; }
                    v.y = sh[e * ROW_PAD + c]; if (++c == 14) { c = 0; ++e; }
                    v.z = sh[e * ROW_PAD + c]; if (++c == 14) { c = 0; ++e; }
                    v.w = sh[e * ROW_PAD + c];
                    og[k] = v;
                }
            } else {
                int nfloat = cnt * 14;
                for (int g = tid; g < nfloat; g += TPB) {
                    int e = g / 14;
                    int c = g - e * 14;
                    out[gbase + g] = sh[e * ROW_PAD + c];
                }
            }
        }
        __syncthreads();
    }
}

extern "C" void kernel_launch(void* const* d_in, const int* in_sizes, int n_in,
                              void* d_out, int out_size) {
    const float* actions = (const float*)d_in[0];
    float* out = (float*)d_out;
    int B = in_sizes[0] / 3;  // actions is [B, 3]

    int blocks = (B + TPB - 1) / TPB;
    sfr_rk4_kernel<<<blocks, TPB>>>(actions, out, B);
}

// round 3
// speedup vs baseline: 3.2058x; 1.1580x over previous
#include <cuda_runtime.h>
#include <cstdint>

// Problem constants (from reference)
#define L0_TOP 0.05f
#define D_CONST 0.0075f
#define DS 0.005f
#define N_STEPS 10

#define TPB 256
#define ROW_FLOATS (TPB * 14)          // 3584 floats per block-row
#define ROW_BYTES  (ROW_FLOATS * 4)    // 14336 bytes

// ODE on the 12-float live state: y = [r0..r2, R00..R22]
// dr = R[:,2]; dR[i,0] = -uy*R[i,2]; dR[i,1] = ux*R[i,2]; dR[i,2] = uy*R[i,0] - ux*R[i,1]
__device__ __forceinline__ void ode_fn(const float* __restrict__ y,
                                       float ux, float uy,
                                       float* __restrict__ d) {
    d[0] = y[3 + 2];
    d[1] = y[3 + 5];
    d[2] = y[3 + 8];
#pragma unroll
    for (int i = 0; i < 3; i++) {
        float Ri0 = y[3 + i * 3 + 0];
        float Ri1 = y[3 + i * 3 + 1];
        float Ri2 = y[3 + i * 3 + 2];
        d[3 + i * 3 + 0] = -uy * Ri2;
        d[3 + i * 3 + 1] =  ux * Ri2;
        d[3 + i * 3 + 2] =  uy * Ri0 - ux * Ri1;
    }
}

__global__ void __launch_bounds__(TPB) sfr_rk4_tma_kernel(
    const float* __restrict__ actions,  // [B, 3]
    float* __restrict__ out,            // [11, B, 14]
    int B)
{
    // Double-buffered packed staging: exact global layout (stride 14 floats).
    __shared__ __align__(16) float sh[2][ROW_FLOATS];

    const int tid = threadIdx.x;
    const int blockStart = blockIdx.x * TPB;
    const int b = blockStart + tid;
    const bool active = (b < B);
    const int cnt = min(TPB, B - blockStart);
    const bool full = (cnt == TPB);

    float ux = 0.f, uy = 0.f;
    if (active) {
        float a1 = actions[b * 3 + 1];
        float a2 = actions[b * 3 + 2];
        const float ld = L0_TOP * D_CONST;   // 0.000375
        ux = a2 / (-ld);
        uy = a1 / ( ld);
    }

    // y0: r = 0, R = I
    float y[12] = {0.f, 0.f, 0.f,
                   1.f, 0.f, 0.f,
                   0.f, 1.f, 0.f,
                   0.f, 0.f, 1.f};

    const float dt = DS;
    const float half_dt = 0.5f * dt;
    const float dt6 = dt * (1.0f / 6.0f);

#pragma unroll 1
    for (int t = 0; t <= N_STEPS; t++) {
        // ---- advance state (t==0 emits y0 unchanged) ----
        if (t > 0) {
            float k1[12], k2[12], k3[12], k4[12], tmp[12];
            ode_fn(y, ux, uy, k1);
#pragma unroll
            for (int i = 0; i < 12; i++) tmp[i] = y[i] + half_dt * k1[i];
            ode_fn(tmp, ux, uy, k2);
#pragma unroll
            for (int i = 0; i < 12; i++) tmp[i] = y[i] + half_dt * k2[i];
            ode_fn(tmp, ux, uy, k3);
#pragma unroll
            for (int i = 0; i < 12; i++) tmp[i] = y[i] + dt * k3[i];
            ode_fn(tmp, ux, uy, k4);
#pragma unroll
            for (int i = 0; i < 12; i++)
                y[i] = y[i] + dt6 * (k1[i] + 2.0f * k2[i] + 2.0f * k3[i] + k4[i]);
        }

        if (full) {
            const int buf = t & 1;

            // Ensure the TMA store issued on this buffer two rows ago has
            // finished READING smem before we overwrite it.
            if (t >= 2 && tid == 0) {
                asm volatile("cp.async.bulk.wait_group.read 1;" ::: "memory");
            }
            __syncthreads();

            // ---- stage packed row: 7x STS.64, stride 56B (conflict-free) ----
            {
                float2* s = reinterpret_cast<float2*>(sh[buf] + tid * 14);
                s[0] = make_float2(y[0],  y[1]);
                s[1] = make_float2(y[2],  y[3]);
                s[2] = make_float2(y[4],  y[5]);
                s[3] = make_float2(y[6],  y[7]);
                s[4] = make_float2(y[8],  y[9]);
                s[5] = make_float2(y[10], y[11]);
                s[6] = make_float2(ux,    uy);
            }
            // Make generic-proxy STS visible to the async (TMA) proxy.
            asm volatile("fence.proxy.async.shared::cta;" ::: "memory");
            __syncthreads();

            // ---- single bulk async store: smem -> gmem (14336B, contiguous) ----
            if (tid == 0) {
                const float* gdst = out + (size_t)t * (size_t)B * 14
                                        + (size_t)blockStart * 14;
                uint32_t ssrc = (uint32_t)__cvta_generic_to_shared(sh[buf]);
                asm volatile(
                    "cp.async.bulk.global.shared::cta.bulk_group [%0], [%1], %2;\n\t"
                    "cp.async.bulk.commit_group;"
                    :: "l"(gdst), "r"(ssrc), "n"(ROW_BYTES)
                    : "memory");
            }
        } else {
            // Tail block (doesn't occur for B % TPB == 0): direct stores.
            if (active) {
                size_t base = (size_t)t * (size_t)B * 14 + (size_t)b * 14;
                float2* o = reinterpret_cast<float2*>(out + base);
                o[0] = make_float2(y[0],  y[1]);
                o[1] = make_float2(y[2],  y[3]);
                o[2] = make_float2(y[4],  y[5]);
                o[3] = make_float2(y[6],  y[7]);
                o[4] = make_float2(y[8],  y[9]);
                o[5] = make_float2(y[10], y[11]);
                o[6] = make_float2(ux,    uy);
            }
        }
    }

    // Drain all outstanding bulk stores before exit.
    if (full && tid == 0) {
        asm volatile("cp.async.bulk.wait_group 0;" ::: "memory");
    }
}

extern "C" void kernel_launch(void* const* d_in, const int* in_sizes, int n_in,
                              void* d_out, int out_size) {
    const float* actions = (const float*)d_in[0];
    float* out = (float*)d_out;
    int B = in_sizes[0] / 3;  // actions is [B, 3]

    int blocks = (B + TPB - 1) / TPB;
    sfr_rk4_tma_kernel<<<blocks, TPB>>>(actions, out, B);
}